// round 2
// baseline (speedup 1.0000x reference)
#include <cuda_runtime.h>
#include <math.h>

// Problem constants
#define B 16
#define L 2048
#define M 32000
#define MP1 32001
#define D 512

// Scratch (static __device__, allocation-free)
__device__ float g_inv_e[MP1];      // 1/max(||emb_w[t]||,1)
__device__ float g_cdot[MP1];       // raw dot(emb_w[M], emb_w[t])
__device__ float g_inv_p[L];        // 1/max(||pos_w[l]||,1)
__device__ float g_logits[B * L];   // masked-row logits, then probs (in place)
__device__ float g_sel[B * D];      // sel_output
__device__ float g_ip[B * M];       // inner products
__device__ float g_loss;

// ---------------------------------------------------------------------------
// K1: row norms for emb_w (32001 rows) and pos_w (2048 rows), plus
//     cdot[t] = dot(emb_w[M], emb_w[t]) fused into the same emb_w read.
//     One warp per row. Also zeroes the loss accumulator.
// ---------------------------------------------------------------------------
__global__ __launch_bounds__(256) void k_norms(const float* __restrict__ emb,
                                               const float* __restrict__ pos) {
    if (blockIdx.x == 0 && threadIdx.x == 0) g_loss = 0.0f;
    int wid  = (blockIdx.x * blockDim.x + threadIdx.x) >> 5;
    int lane = threadIdx.x & 31;
    if (wid < MP1) {
        const float4* row = (const float4*)(emb + (size_t)wid * D);
        const float4* qm  = (const float4*)(emb + (size_t)M * D);
        float ss = 0.0f, dq = 0.0f;
#pragma unroll
        for (int i = 0; i < 4; i++) {
            float4 v = row[lane + 32 * i];
            float4 q = qm[lane + 32 * i];
            ss += v.x * v.x + v.y * v.y + v.z * v.z + v.w * v.w;
            dq += v.x * q.x + v.y * q.y + v.z * q.z + v.w * q.w;
        }
#pragma unroll
        for (int o = 16; o; o >>= 1) {
            ss += __shfl_xor_sync(0xffffffffu, ss, o);
            dq += __shfl_xor_sync(0xffffffffu, dq, o);
        }
        if (lane == 0) {
            g_inv_e[wid] = 1.0f / fmaxf(sqrtf(ss), 1.0f);
            g_cdot[wid]  = dq;
        }
    } else if (wid < MP1 + L) {
        int l = wid - MP1;
        const float4* row = (const float4*)(pos + (size_t)l * D);
        float ss = 0.0f;
#pragma unroll
        for (int i = 0; i < 4; i++) {
            float4 v = row[lane + 32 * i];
            ss += v.x * v.x + v.y * v.y + v.z * v.z + v.w * v.w;
        }
#pragma unroll
        for (int o = 16; o; o >>= 1) ss += __shfl_xor_sync(0xffffffffu, ss, o);
        if (lane == 0) g_inv_p[l] = 1.0f / fmaxf(sqrtf(ss), 1.0f);
    }
}

// ---------------------------------------------------------------------------
// K2: masked-row attention logits. grid (L/8, B), block 256 (8 warps, 1 m each).
//     logit[b][m] = (cdot[t]*inv_e[t]*inv_e[M] + (pw[p].pw[m])*inv_p[p]*inv_p[m]) / 32
//     where p = mask_idx[b], t = (m==p) ? M : x[b][m].
// ---------------------------------------------------------------------------
__global__ __launch_bounds__(256) void k_logits(const float* __restrict__ pos,
                                                const int* __restrict__ x,
                                                const int* __restrict__ mask_idx) {
    __shared__ float s_pw[D];
    int b = blockIdx.y;
    int p = mask_idx[b];
    for (int i = threadIdx.x; i < D; i += 256) s_pw[i] = pos[(size_t)p * D + i];
    __syncthreads();

    int m    = blockIdx.x * 8 + (threadIdx.x >> 5);
    int lane = threadIdx.x & 31;
    int t    = (m == p) ? M : x[b * L + m];

    const float4* prow = (const float4*)(pos + (size_t)m * D);
    const float4* sp   = (const float4*)s_pw;
    float pd = 0.0f;
#pragma unroll
    for (int i = 0; i < 4; i++) {
        float4 v = prow[lane + 32 * i];
        float4 w = sp[lane + 32 * i];
        pd += v.x * w.x + v.y * w.y + v.z * w.z + v.w * w.w;
    }
#pragma unroll
    for (int o = 16; o; o >>= 1) pd += __shfl_xor_sync(0xffffffffu, pd, o);
    if (lane == 0) {
        float c = g_cdot[t] * g_inv_e[t] * g_inv_e[M];
        float q = pd * g_inv_p[m] * g_inv_p[p];
        g_logits[b * L + m] = (c + q) * (1.0f / 32.0f);  // 1/sqrt(2D)
    }
}

// ---------------------------------------------------------------------------
// K3: softmax over L per batch (in place), and zero g_sel[b]. grid B, block 1024.
// ---------------------------------------------------------------------------
__global__ __launch_bounds__(1024) void k_softmax() {
    __shared__ float sred[32];
    int b = blockIdx.x, tid = threadIdx.x, lane = tid & 31, w = tid >> 5;
    float* lg = g_logits + b * L;
    float v0 = lg[tid], v1 = lg[tid + 1024];

    float mx = fmaxf(v0, v1);
#pragma unroll
    for (int o = 16; o; o >>= 1) mx = fmaxf(mx, __shfl_xor_sync(0xffffffffu, mx, o));
    if (lane == 0) sred[w] = mx;
    __syncthreads();
    if (w == 0) {
        float m2 = sred[lane];
#pragma unroll
        for (int o = 16; o; o >>= 1) m2 = fmaxf(m2, __shfl_xor_sync(0xffffffffu, m2, o));
        if (lane == 0) sred[0] = m2;
    }
    __syncthreads();
    mx = sred[0];

    float e0 = expf(v0 - mx), e1 = expf(v1 - mx);
    float s = e0 + e1;
#pragma unroll
    for (int o = 16; o; o >>= 1) s += __shfl_xor_sync(0xffffffffu, s, o);
    __syncthreads();
    if (lane == 0) sred[w] = s;
    __syncthreads();
    if (w == 0) {
        float s2 = sred[lane];
#pragma unroll
        for (int o = 16; o; o >>= 1) s2 += __shfl_xor_sync(0xffffffffu, s2, o);
        if (lane == 0) sred[0] = s2;
    }
    __syncthreads();
    float inv = 1.0f / sred[0];
    lg[tid] = e0 * inv;
    lg[tid + 1024] = e1 * inv;
    if (tid < D) g_sel[b * D + tid] = 0.0f;
}

// ---------------------------------------------------------------------------
// K4: sel_output[b] = sum_m p[b][m] * inv_e[t] * emb_w[t].
//     grid (L/64, B), block 512 (one thread per d), 64 m per block, atomic merge.
// ---------------------------------------------------------------------------
__global__ __launch_bounds__(512) void k_selout(const float* __restrict__ emb,
                                                const int* __restrict__ x,
                                                const int* __restrict__ mask_idx) {
    __shared__ float s_p[64];
    __shared__ int   s_t[64];
    int b = blockIdx.y, m0 = blockIdx.x * 64;
    int p = mask_idx[b];
    if (threadIdx.x < 64) {
        int m = m0 + threadIdx.x;
        int t = (m == p) ? M : x[b * L + m];
        s_t[threadIdx.x] = t;
        s_p[threadIdx.x] = g_logits[b * L + m] * g_inv_e[t];
    }
    __syncthreads();
    int d = threadIdx.x;
    float acc = 0.0f;
#pragma unroll 4
    for (int i = 0; i < 64; i++) {
        acc += s_p[i] * emb[(size_t)s_t[i] * D + d];
    }
    atomicAdd(&g_sel[b * D + d], acc);
}

// ---------------------------------------------------------------------------
// K5: inner_prod[b][j] = (sel[b] . emb_w[j]) * inv_e[j] for j < M.
//     grid M/8, block 256. All 16 sel rows cached in smem; each warp owns one
//     j, reads emb row ONCE, dots against all 16 batches.
// ---------------------------------------------------------------------------
__global__ __launch_bounds__(256) void k_ip(const float* __restrict__ emb) {
    __shared__ float s_sel[B * D];  // 32 KB
    for (int i = threadIdx.x; i < B * D; i += 256) s_sel[i] = g_sel[i];
    __syncthreads();

    int j    = blockIdx.x * 8 + (threadIdx.x >> 5);
    int lane = threadIdx.x & 31;
    const float4* row = (const float4*)(emb + (size_t)j * D);
    float4 v[4];
#pragma unroll
    for (int i = 0; i < 4; i++) v[i] = row[lane + 32 * i];
    float invj = g_inv_e[j];

#pragma unroll
    for (int b = 0; b < B; b++) {
        const float4* sb = (const float4*)(s_sel + b * D);
        float dsum = 0.0f;
#pragma unroll
        for (int i = 0; i < 4; i++) {
            float4 w = sb[lane + 32 * i];
            dsum += v[i].x * w.x + v[i].y * w.y + v[i].z * w.z + v[i].w * w.w;
        }
#pragma unroll
        for (int o = 16; o; o >>= 1) dsum += __shfl_xor_sync(0xffffffffu, dsum, o);
        if (lane == 0) g_ip[b * M + j] = dsum * invj;
    }
}

// ---------------------------------------------------------------------------
// K6: per-batch log-softmax over M and NLL accumulation. grid B, block 1024.
// ---------------------------------------------------------------------------
__global__ __launch_bounds__(1024) void k_loss(const int* __restrict__ x,
                                               const int* __restrict__ mask_idx) {
    __shared__ float sred[32];
    int b = blockIdx.x, tid = threadIdx.x, lane = tid & 31, w = tid >> 5;
    const float* ip = g_ip + b * M;

    float mx = -1e30f;
    for (int i = tid; i < M; i += 1024) mx = fmaxf(mx, ip[i]);
#pragma unroll
    for (int o = 16; o; o >>= 1) mx = fmaxf(mx, __shfl_xor_sync(0xffffffffu, mx, o));
    if (lane == 0) sred[w] = mx;
    __syncthreads();
    if (w == 0) {
        float m2 = sred[lane];
#pragma unroll
        for (int o = 16; o; o >>= 1) m2 = fmaxf(m2, __shfl_xor_sync(0xffffffffu, m2, o));
        if (lane == 0) sred[0] = m2;
    }
    __syncthreads();
    float bmx = sred[0];

    float s = 0.0f;
    for (int i = tid; i < M; i += 1024) s += expf(ip[i] - bmx);
#pragma unroll
    for (int o = 16; o; o >>= 1) s += __shfl_xor_sync(0xffffffffu, s, o);
    __syncthreads();
    if (lane == 0) sred[w] = s;
    __syncthreads();
    if (w == 0) {
        float s2 = sred[lane];
#pragma unroll
        for (int o = 16; o; o >>= 1) s2 += __shfl_xor_sync(0xffffffffu, s2, o);
        if (lane == 0) sred[0] = s2;
    }
    __syncthreads();
    if (tid == 0) {
        int t = x[b * L + mask_idx[b]];
        float logp = ip[t] - bmx - logf(sred[0]);
        atomicAdd(&g_loss, -logp * (1.0f / (float)B));
    }
}

// ---------------------------------------------------------------------------
// K7: write flattened (loss, sel_output) to d_out.
// ---------------------------------------------------------------------------
__global__ void k_out(float* __restrict__ out, int out_size) {
    int i = blockIdx.x * blockDim.x + threadIdx.x;
    if (i >= out_size) return;
    if (out_size >= B * D + 1) {
        if (i == 0)            out[0] = g_loss;
        else if (i <= B * D)   out[i] = g_sel[i - 1];
        else                   out[i] = 0.0f;
    } else if (out_size == B * D) {
        out[i] = g_sel[i];
    } else {
        out[i] = (i == 0) ? g_loss : 0.0f;
    }
}

// ---------------------------------------------------------------------------
extern "C" void kernel_launch(void* const* d_in, const int* in_sizes, int n_in,
                              void* d_out, int out_size) {
    const int*   x    = nullptr;
    const int*   midx = nullptr;
    const float* emb  = nullptr;
    const float* pos  = nullptr;
    for (int i = 0; i < n_in; i++) {
        switch (in_sizes[i]) {
            case B * L:     x    = (const int*)d_in[i];   break;
            case B:         midx = (const int*)d_in[i];   break;
            case MP1 * D:   emb  = (const float*)d_in[i]; break;
            case L * D:     pos  = (const float*)d_in[i]; break;
            default: break;
        }
    }
    float* out = (float*)d_out;

    // K1: norms + cdot (one warp per row, 34049 rows)
    {
        int warps = MP1 + L;
        int blocks = (warps + 7) / 8;
        k_norms<<<blocks, 256>>>(emb, pos);
    }
    // K2: masked-row logits
    {
        dim3 grid(L / 8, B);
        k_logits<<<grid, 256>>>(pos, x, midx);
    }
    // K3: softmax per batch + zero sel
    k_softmax<<<B, 1024>>>();
    // K4: weighted gather sum -> sel_output
    {
        dim3 grid(L / 64, B);
        k_selout<<<grid, 512>>>(emb, x, midx);
    }
    // K5: inner products vs full vocab
    k_ip<<<M / 8, 256>>>(emb);
    // K6: log-softmax + loss
    k_loss<<<B, 1024>>>(x, midx);
    // K7: emit outputs
    {
        int n = out_size;
        k_out<<<(n + 255) / 256, 256>>>(out, n);
    }
}

// round 4
// speedup vs baseline: 1.0184x; 1.0184x over previous
#include <cuda_runtime.h>
#include <math.h>

// Problem constants
#define B 16
#define L 2048
#define M 32000
#define MP1 32001
#define D 512

// Scratch (static __device__, allocation-free)
__device__ float g_inv_e[MP1];      // 1/max(||emb_w[t]||,1)
__device__ float g_cdot[MP1];       // raw dot(emb_w[M], emb_w[t])
__device__ float g_inv_p[L];        // 1/max(||pos_w[l]||,1)
__device__ float g_logits[B * L];   // masked-row logits, then probs (in place)
__device__ float g_sel[B * D];      // sel_output
__device__ float g_ip[B * M];       // inner products

// ---------------------------------------------------------------------------
// K1: row norms for emb_w (32001 rows) and pos_w (2048 rows), plus
//     cdot[t] = dot(emb_w[M], emb_w[t]) fused into the same emb_w read.
//     One warp per row.
// ---------------------------------------------------------------------------
__global__ __launch_bounds__(256) void k_norms(const float* __restrict__ emb,
                                               const float* __restrict__ pos) {
    int wid  = (blockIdx.x * blockDim.x + threadIdx.x) >> 5;
    int lane = threadIdx.x & 31;
    if (wid < MP1) {
        const float4* row = (const float4*)(emb + (size_t)wid * D);
        const float4* qm  = (const float4*)(emb + (size_t)M * D);
        float ss = 0.0f, dq = 0.0f;
#pragma unroll
        for (int i = 0; i < 4; i++) {
            float4 v = row[lane + 32 * i];
            float4 q = qm[lane + 32 * i];
            ss += v.x * v.x + v.y * v.y + v.z * v.z + v.w * v.w;
            dq += v.x * q.x + v.y * q.y + v.z * q.z + v.w * q.w;
        }
#pragma unroll
        for (int o = 16; o; o >>= 1) {
            ss += __shfl_xor_sync(0xffffffffu, ss, o);
            dq += __shfl_xor_sync(0xffffffffu, dq, o);
        }
        if (lane == 0) {
            g_inv_e[wid] = 1.0f / fmaxf(sqrtf(ss), 1.0f);
            g_cdot[wid]  = dq;
        }
    } else if (wid < MP1 + L) {
        int l = wid - MP1;
        const float4* row = (const float4*)(pos + (size_t)l * D);
        float ss = 0.0f;
#pragma unroll
        for (int i = 0; i < 4; i++) {
            float4 v = row[lane + 32 * i];
            ss += v.x * v.x + v.y * v.y + v.z * v.z + v.w * v.w;
        }
#pragma unroll
        for (int o = 16; o; o >>= 1) ss += __shfl_xor_sync(0xffffffffu, ss, o);
        if (lane == 0) g_inv_p[l] = 1.0f / fmaxf(sqrtf(ss), 1.0f);
    }
}

// ---------------------------------------------------------------------------
// K2: masked-row attention logits, ALL batches in one pass over pos_w.
//     grid L/8, block 256 (8 warps, 1 m each). All 16 masked p-rows staged in
//     smem; each warp dots its m-row against all 16.
//     logit[b][m] = (cdot[t]*inv_e[t]*inv_e[M] + (pw[p_b].pw[m])*inv_p[p_b]*inv_p[m]) / 32
// ---------------------------------------------------------------------------
__global__ __launch_bounds__(256) void k_logits(const float* __restrict__ pos,
                                                const int* __restrict__ x,
                                                const int* __restrict__ mask_idx) {
    __shared__ float s_pw[B][D];   // 32 KB
    __shared__ int   s_pidx[B];
    __shared__ float s_pinv[B];
    int tid = threadIdx.x;
    if (tid < B) {
        int p = mask_idx[tid];
        s_pidx[tid] = p;
        s_pinv[tid] = g_inv_p[p];
    }
    __syncthreads();
    for (int i = tid; i < B * D; i += 256) {
        int b = i >> 9, d = i & (D - 1);
        s_pw[b][d] = pos[(size_t)s_pidx[b] * D + d];
    }
    __syncthreads();

    int w = tid >> 5, lane = tid & 31;
    int m = blockIdx.x * 8 + w;

    const float4* prow = (const float4*)(pos + (size_t)m * D);
    float4 v[4];
#pragma unroll
    for (int i = 0; i < 4; i++) v[i] = prow[lane + 32 * i];
    float invm  = g_inv_p[m];
    float inv_eM = g_inv_e[M];

    // Lane l (<16) precomputes the content term for batch l
    float c_l = 0.0f;
    if (lane < B) {
        int t = (m == s_pidx[lane]) ? M : x[lane * L + m];
        c_l = g_cdot[t] * g_inv_e[t];
    }

#pragma unroll
    for (int b = 0; b < B; b++) {
        const float4* sp = (const float4*)s_pw[b];
        float pd = 0.0f;
#pragma unroll
        for (int i = 0; i < 4; i++) {
            float4 u = sp[lane + 32 * i];
            pd += v[i].x * u.x + v[i].y * u.y + v[i].z * u.z + v[i].w * u.w;
        }
#pragma unroll
        for (int o = 16; o; o >>= 1) pd += __shfl_xor_sync(0xffffffffu, pd, o);
        float cb = __shfl_sync(0xffffffffu, c_l, b);
        if (lane == 0)
            g_logits[b * L + m] = (cb * inv_eM + pd * invm * s_pinv[b]) * (1.0f / 32.0f);
    }
}

// ---------------------------------------------------------------------------
// K3: softmax over L per batch (in place), zero g_sel[b], zero out[0] (+tail).
// ---------------------------------------------------------------------------
__global__ __launch_bounds__(1024) void k_softmax(float* __restrict__ out, int out_size) {
    __shared__ float sred[32];
    int b = blockIdx.x, tid = threadIdx.x, lane = tid & 31, w = tid >> 5;
    float* lg = g_logits + b * L;
    float v0 = lg[tid], v1 = lg[tid + 1024];

    float mx = fmaxf(v0, v1);
#pragma unroll
    for (int o = 16; o; o >>= 1) mx = fmaxf(mx, __shfl_xor_sync(0xffffffffu, mx, o));
    if (lane == 0) sred[w] = mx;
    __syncthreads();
    if (w == 0) {
        float m2 = sred[lane];
#pragma unroll
        for (int o = 16; o; o >>= 1) m2 = fmaxf(m2, __shfl_xor_sync(0xffffffffu, m2, o));
        if (lane == 0) sred[0] = m2;
    }
    __syncthreads();
    mx = sred[0];

    float e0 = expf(v0 - mx), e1 = expf(v1 - mx);
    float s = e0 + e1;
#pragma unroll
    for (int o = 16; o; o >>= 1) s += __shfl_xor_sync(0xffffffffu, s, o);
    __syncthreads();
    if (lane == 0) sred[w] = s;
    __syncthreads();
    if (w == 0) {
        float s2 = sred[lane];
#pragma unroll
        for (int o = 16; o; o >>= 1) s2 += __shfl_xor_sync(0xffffffffu, s2, o);
        if (lane == 0) sred[0] = s2;
    }
    __syncthreads();
    float inv = 1.0f / sred[0];
    lg[tid] = e0 * inv;
    lg[tid + 1024] = e1 * inv;
    if (tid < D) g_sel[b * D + tid] = 0.0f;
    if (b == 0) {
        if (tid == 0) out[0] = 0.0f;                         // re-zeroed every replay
        for (int i = B * D + 1 + tid; i < out_size; i += 1024) out[i] = 0.0f;
    }
}

// ---------------------------------------------------------------------------
// K4: sel_output[b] = sum_m p[b][m] * inv_e[t] * emb_w[t].
//     grid (L/64, B), block 128: each thread owns one float4 of d, streams 64
//     rows with LDG.128 (deep MLP), atomic merge into g_sel.
// ---------------------------------------------------------------------------
__global__ __launch_bounds__(128) void k_selout(const float* __restrict__ emb,
                                                const int* __restrict__ x,
                                                const int* __restrict__ mask_idx) {
    __shared__ float s_p[64];
    __shared__ int   s_t[64];
    int b = blockIdx.y, m0 = blockIdx.x * 64;
    int p = mask_idx[b];
    if (threadIdx.x < 64) {
        int m = m0 + threadIdx.x;
        int t = (m == p) ? M : x[b * L + m];
        s_t[threadIdx.x] = t;
        s_p[threadIdx.x] = g_logits[b * L + m] * g_inv_e[t];
    }
    __syncthreads();

    const float4* emb4 = (const float4*)emb;
    int c = threadIdx.x;                       // float4 column 0..127
    float4 acc = make_float4(0.f, 0.f, 0.f, 0.f);
#pragma unroll 8
    for (int i = 0; i < 64; i++) {
        float4 v = emb4[(size_t)s_t[i] * (D / 4) + c];
        float  w = s_p[i];
        acc.x += w * v.x; acc.y += w * v.y; acc.z += w * v.z; acc.w += w * v.w;
    }
    float* dst = g_sel + b * D + c * 4;
    atomicAdd(dst + 0, acc.x);
    atomicAdd(dst + 1, acc.y);
    atomicAdd(dst + 2, acc.z);
    atomicAdd(dst + 3, acc.w);
}

// ---------------------------------------------------------------------------
// K5: inner_prod[b][j] = (sel[b] . emb_w[j]) * inv_e[j] for j < M.
//     grid M/8, block 256. All 16 sel rows cached in smem; each warp owns one
//     j, reads emb row ONCE, dots against all 16 batches.
//     Block 0 additionally copies sel_output into out[1..B*D].
// ---------------------------------------------------------------------------
__global__ __launch_bounds__(256) void k_ip(const float* __restrict__ emb,
                                            float* __restrict__ out, int out_size) {
    __shared__ float s_sel[B * D];  // 32 KB
    for (int i = threadIdx.x; i < B * D; i += 256) s_sel[i] = g_sel[i];
    __syncthreads();

    if (blockIdx.x == 0) {
        int lim = out_size - 1; if (lim > B * D) lim = B * D;
        for (int i = threadIdx.x; i < lim; i += 256) out[1 + i] = s_sel[i];
    }

    int j    = blockIdx.x * 8 + (threadIdx.x >> 5);
    int lane = threadIdx.x & 31;
    const float4* row = (const float4*)(emb + (size_t)j * D);
    float4 v[4];
#pragma unroll
    for (int i = 0; i < 4; i++) v[i] = row[lane + 32 * i];
    float invj = g_inv_e[j];

#pragma unroll
    for (int b = 0; b < B; b++) {
        const float4* sb = (const float4*)(s_sel + b * D);
        float dsum = 0.0f;
#pragma unroll
        for (int i = 0; i < 4; i++) {
            float4 u = sb[lane + 32 * i];
            dsum += v[i].x * u.x + v[i].y * u.y + v[i].z * u.z + v[i].w * u.w;
        }
#pragma unroll
        for (int o = 16; o; o >>= 1) dsum += __shfl_xor_sync(0xffffffffu, dsum, o);
        if (lane == 0) g_ip[b * M + j] = dsum * invj;
    }
}

// ---------------------------------------------------------------------------
// K6: per-batch log-softmax over M and NLL accumulation straight into out[0].
// ---------------------------------------------------------------------------
__global__ __launch_bounds__(1024) void k_loss(const int* __restrict__ x,
                                               const int* __restrict__ mask_idx,
                                               float* __restrict__ out) {
    __shared__ float sred[32];
    int b = blockIdx.x, tid = threadIdx.x, lane = tid & 31, w = tid >> 5;
    const float* ip = g_ip + b * M;

    float mx = -1e30f;
    for (int i = tid; i < M; i += 1024) mx = fmaxf(mx, ip[i]);
#pragma unroll
    for (int o = 16; o; o >>= 1) mx = fmaxf(mx, __shfl_xor_sync(0xffffffffu, mx, o));
    if (lane == 0) sred[w] = mx;
    __syncthreads();
    if (w == 0) {
        float m2 = sred[lane];
#pragma unroll
        for (int o = 16; o; o >>= 1) m2 = fmaxf(m2, __shfl_xor_sync(0xffffffffu, m2, o));
        if (lane == 0) sred[0] = m2;
    }
    __syncthreads();
    float bmx = sred[0];

    float s = 0.0f;
    for (int i = tid; i < M; i += 1024) s += expf(ip[i] - bmx);
#pragma unroll
    for (int o = 16; o; o >>= 1) s += __shfl_xor_sync(0xffffffffu, s, o);
    __syncthreads();
    if (lane == 0) sred[w] = s;
    __syncthreads();
    if (w == 0) {
        float s2 = sred[lane];
#pragma unroll
        for (int o = 16; o; o >>= 1) s2 += __shfl_xor_sync(0xffffffffu, s2, o);
        if (lane == 0) sred[0] = s2;
    }
    __syncthreads();
    if (tid == 0) {
        int t = x[b * L + mask_idx[b]];
        float logp = ip[t] - bmx - logf(sred[0]);
        atomicAdd(out, -logp * (1.0f / (float)B));
    }
}

// ---------------------------------------------------------------------------
extern "C" void kernel_launch(void* const* d_in, const int* in_sizes, int n_in,
                              void* d_out, int out_size) {
    const int*   x    = nullptr;
    const int*   midx = nullptr;
    const float* emb  = nullptr;
    const float* pos  = nullptr;
    for (int i = 0; i < n_in; i++) {
        switch (in_sizes[i]) {
            case B * L:     x    = (const int*)d_in[i];   break;
            case B:         midx = (const int*)d_in[i];   break;
            case MP1 * D:   emb  = (const float*)d_in[i]; break;
            case L * D:     pos  = (const float*)d_in[i]; break;
            default: break;
        }
    }
    float* out = (float*)d_out;

    // K1: norms + cdot (one warp per row, 34049 rows)
    {
        int warps = MP1 + L;
        int blocks = (warps + 7) / 8;
        k_norms<<<blocks, 256>>>(emb, pos);
    }
    // K2: masked-row logits, single pass over pos_w for all batches
    k_logits<<<L / 8, 256>>>(pos, x, midx);
    // K3: softmax per batch + zero sel + zero out[0]/tail
    k_softmax<<<B, 1024>>>(out, out_size);
    // K4: weighted gather sum -> sel_output (float4 streams)
    {
        dim3 grid(L / 64, B);
        k_selout<<<grid, 128>>>(emb, x, midx);
    }
    // K5: inner products vs full vocab (+ copy sel into out)
    k_ip<<<M / 8, 256>>>(emb, out, out_size);
    // K6: log-softmax + loss -> out[0]
    k_loss<<<B, 1024>>>(x, midx, out);
}